// round 3
// baseline (speedup 1.0000x reference)
#include <cuda_runtime.h>

#define IMG     512
#define WSTRIP  128
#define HSEG    128
#define HALO    5
#define SROW    138

typedef unsigned long long u64;

static __device__ __forceinline__ u64 pk(float lo, float hi) {
    u64 r; asm("mov.b64 %0, {%1, %2};" : "=l"(r) : "f"(lo), "f"(hi)); return r;
}
static __device__ __forceinline__ void upk(u64 v, float& lo, float& hi) {
    asm("mov.b64 {%0, %1}, %2;" : "=f"(lo), "=f"(hi) : "l"(v));
}
static __device__ __forceinline__ u64 fma2(u64 a, u64 b, u64 c) {
    u64 d; asm("fma.rn.f32x2 %0, %1, %2, %3;" : "=l"(d) : "l"(a), "l"(b), "l"(c)); return d;
}

// Load one global row into a register stage set (zero-filled outside bounds).
#define LOADROW(SP, SQ, SP1, SQ1, R) do {                                   \
    const int _r = (R);                                                     \
    SP = 0.f; SQ = 0.f; SP1 = 0.f; SQ1 = 0.f;                               \
    if (_r >= ract_lo && _r <= ract_hi) {                                   \
        if (v0) { const int _i = _r * IMG + gc0; SP  = p0[_i]; SQ  = gf[_i]; } \
        if (v1) { const int _i = _r * IMG + gc1; SP1 = gb[_i]; SQ1 = gf[_i]; } \
    }                                                                       \
} while (0)

// Store a staged row into smem buffer NB as pre-packed product channels.
//   X side (t<138):  s0=(a, a*a)   s1=(f,   a*f)
//   Y side:          s0=(b, b*b)   s1=(f*f, b*f)
#define STOREROW(SP, SQ, SP1, SQ1, NB) do {                                 \
    const float _p = (SP), _q = (SQ);                                       \
    s0[NB][jside][jc0] = pk(_p, _p * _p);                                   \
    s1[NB][jside][jc0] = isX ? pk(_q, _p * _q) : pk(_q * _q, _p * _q);      \
    if (v1j) {                                                              \
        const float _p1 = (SP1), _q1 = (SQ1);                               \
        s0[NB][1][118 + t] = pk(_p1, _p1 * _p1);                            \
        s1[NB][1][118 + t] = pk(_q1 * _q1, _p1 * _q1);                      \
    }                                                                       \
} while (0)

__global__ void __launch_bounds__(256, 3)
ssim_fused_kernel(const float* __restrict__ A, const float* __restrict__ B,
                  const float* __restrict__ F, float* __restrict__ out,
                  float scale)
{
    constexpr float W[11] = {0.00102838f, 0.00759876f, 0.03600077f, 0.10936069f,
                             0.21300553f, 0.26601172f, 0.21300553f, 0.10936069f,
                             0.03600077f, 0.00759876f, 0.00102838f};
    constexpr float C1 = 0.0001f, C2 = 0.0009f;

    const int t    = threadIdx.x;
    const int side = t & 1;          // 0: (a,a2)/(f,af)   1: (b,b2)/(f2,bf)
    const int col  = t >> 1;         // output column within strip (0..127)
    const int x0 = blockIdx.x * WSTRIP;
    const int y0 = blockIdx.y * HSEG;
    const int y1 = y0 + HSEG;
    const size_t poff = (size_t)blockIdx.z * (size_t)(IMG * IMG);
    const float* ga = A + poff;
    const float* gb = B + poff;
    const float* gf = F + poff;

    // ping-pong single-row buffers, 2 sides, pre-packed channels
    __shared__ u64 s0[2][2][SROW];
    __shared__ u64 s1[2][2][SROW];
    __shared__ float wpart[8];

    u64 W2[6];
#pragma unroll
    for (int j = 0; j < 6; ++j) W2[j] = pk(W[j], W[j]);

    // per-thread vertical ring: 2 packed channels x 11 pending output rows
    u64 r0[11], r1[11];
#pragma unroll
    for (int s = 0; s < 11; ++s) { r0[s] = 0; r1[s] = 0; }

    float ssum = 0.0f;

    const int ract_lo = (y0 - HALO) < 0 ? 0 : (y0 - HALO);
    const int ract_hi = (y1 + HALO - 1) > (IMG - 1) ? (IMG - 1) : (y1 + HALO - 1);

    // staging job assignment: 276 jobs = 138 X-cols + 138 Y-cols
    const bool isX   = (t < SROW);            // job0 side
    const int  jside = isX ? 0 : 1;
    const int  jc0   = isX ? t : (t - SROW);  // smem column 0..137
    const int  gc0   = x0 - HALO + jc0;
    const bool v0    = (gc0 >= 0) && (gc0 < IMG);
    const float* p0  = isX ? ga : gb;
    const bool v1j   = (t < 20);              // job1: Y cols 118..137
    const int  gc1   = x0 - HALO + 118 + t;
    const bool v1    = v1j && (gc1 >= 0) && (gc1 < IMG);

    const int base    = ((y0 - HALO + 11) / 11) * 11 - 11;   // multiple of 11 <= y0-5
    const int nchunks = (y1 + HALO - base + 10) / 11;

    // register stage sets (S0 used on even phases, S1 on odd; swapped per chunk)
    float a0p, a0q, a0p1, a0q1;
    float a1p, a1q, a1p1, a1q1;

    // ---- prologue: row base -> smem buf0; base+1 -> S0; base+2 -> S1 ----
    {
        float tp, tq, tp1, tq1;
        LOADROW(tp, tq, tp1, tq1, base);
        STOREROW(tp, tq, tp1, tq1, 0);
    }
    LOADROW(a0p, a0q, a0p1, a0q1, base + 1);
    LOADROW(a1p, a1q, a1p1, a1q1, base + 2);
    __syncthreads();

#pragma unroll 1
    for (int chk = 0; chk < nchunks; ++chk) {
        const int rbase = base + chk * 11;
#pragma unroll
        for (int p = 0; p < 11; ++p) {
            const int row = rbase + p;
            const int cur = (chk + p) & 1;
            const int nxt = cur ^ 1;

            // 1) stage row+1 into the other buffer, then refill the stage set
            //    with row+3 (two phases of latency cover).
            if ((p & 1) == 0) {
                STOREROW(a0p, a0q, a0p1, a0q1, nxt);
                LOADROW(a0p, a0q, a0p1, a0q1, row + 3);
            } else {
                STOREROW(a1p, a1q, a1p1, a1q1, nxt);
                LOADROW(a1p, a1q, a1p1, a1q1, row + 3);
            }

            // 2) horizontal conv (2 packed channels) + vertical scatter
            if (row >= ract_lo && row <= ract_hi) {
                const u64* m0 = s0[cur][side];
                const u64* m1 = s1[cur][side];
                u64 h0 = 0, h1 = 0;
#pragma unroll
                for (int j = 0; j < 11; ++j) {
                    const u64 w2 = W2[j < 6 ? j : 10 - j];
                    h0 = fma2(m0[col + j], w2, h0);
                    h1 = fma2(m1[col + j], w2, h1);
                }
#pragma unroll
                for (int j = 0; j < 11; ++j) {
                    const int s  = (p + 6 + j) % 11;
                    const u64 w2 = W2[j < 6 ? j : 10 - j];
                    r0[s] = fma2(h0, w2, r0[s]);
                    r1[s] = fma2(h1, w2, r1[s]);
                }
            }

            // 3) output row o = row-5 completes in slot (p+6)%11
            {
                const int o  = row - HALO;
                const int sd = (p + 6) % 11;
                if (o >= y0 && o < y1) {
                    float mu1, E11; upk(r0[sd], mu1, E11);   // (Σw·v, Σw·v²)
                    float lo,  E12; upk(r1[sd], lo,  E12);   // even:(muF,Saf) odd:(EF2,Sbf)
                    const float ot = __shfl_xor_sync(0xffffffffu, lo, 1);
                    const float mu2 = side ? ot : lo;
                    const float E22 = side ? lo : ot;
                    const float m12  = mu1 * mu2;
                    const float mu1s = mu1 * mu1;
                    const float mu2s = mu2 * mu2;
                    const float num  = fmaf(2.0f, m12, C1) * fmaf(2.0f, E12 - m12, C2);
                    const float den  = (mu1s + mu2s + C1)
                                     * (((E11 - mu1s) + (E22 - mu2s)) + C2);
                    ssum += __fdividef(num, den);
                }
                r0[sd] = 0; r1[sd] = 0;
            }

            __syncthreads();
        }
        // chunk length 11 is odd -> swap stage sets to keep phase parity static
        { float x;
          x = a0p;  a0p  = a1p;  a1p  = x;
          x = a0q;  a0q  = a1q;  a1q  = x;
          x = a0p1; a0p1 = a1p1; a1p1 = x;
          x = a0q1; a0q1 = a1q1; a1q1 = x; }
    }

    // block reduction -> one atomic per block
    const unsigned lane = t & 31u;
    const unsigned wid  = (unsigned)t >> 5;
#pragma unroll
    for (int off = 16; off; off >>= 1)
        ssum += __shfl_down_sync(0xffffffffu, ssum, off);
    if (lane == 0) wpart[wid] = ssum;
    __syncthreads();
    if (t == 0) {
        float v = 0.f;
#pragma unroll
        for (int w = 0; w < 8; ++w) v += wpart[w];
        atomicAdd(out, v * scale);
    }
}

__global__ void zero_kernel(float* out) { *out = 0.0f; }

extern "C" void kernel_launch(void* const* d_in, const int* in_sizes, int n_in,
                              void* d_out, int out_size)
{
    const float* A = (const float*)d_in[0];
    const float* B = (const float*)d_in[1];
    const float* F = (const float*)d_in[2];
    float* out = (float*)d_out;

    const int nplanes = in_sizes[0] / (IMG * IMG);   // 48
    const float scale = 0.5f / (float)in_sizes[0];

    zero_kernel<<<1, 1>>>(out);
    dim3 grid(IMG / WSTRIP, IMG / HSEG, nplanes);
    ssim_fused_kernel<<<grid, 256>>>(A, B, F, out, scale);
}

// round 4
// speedup vs baseline: 1.8385x; 1.8385x over previous
#include <cuda_runtime.h>

#define IMG     512
#define WSTRIP  128
#define HSEG    128
#define HALO    5
#define SROW    138

typedef unsigned long long u64;

static __device__ __forceinline__ u64 pk(float lo, float hi) {
    u64 r; asm("mov.b64 %0, {%1, %2};" : "=l"(r) : "f"(lo), "f"(hi)); return r;
}
static __device__ __forceinline__ void upk(u64 v, float& lo, float& hi) {
    asm("mov.b64 {%0, %1}, %2;" : "=f"(lo), "=f"(hi) : "l"(v));
}
static __device__ __forceinline__ u64 fma2(u64 a, u64 b, u64 c) {
    u64 d; asm("fma.rn.f32x2 %0, %1, %2, %3;" : "=l"(d) : "l"(a), "l"(b), "l"(c)); return d;
}
static __device__ __forceinline__ u64 mul2(u64 a, u64 b) {
    u64 d; asm("mul.rn.f32x2 %0, %1, %2;" : "=l"(d) : "l"(a), "l"(b)); return d;
}

__global__ void __launch_bounds__(128, 4)
ssim_fused_kernel(const float* __restrict__ A, const float* __restrict__ B,
                  const float* __restrict__ F, float* __restrict__ out,
                  float scale)
{
    constexpr float W[11] = {0.00102838f, 0.00759876f, 0.03600077f, 0.10936069f,
                             0.21300553f, 0.26601172f, 0.21300553f, 0.10936069f,
                             0.03600077f, 0.00759876f, 0.00102838f};
    constexpr float C1 = 0.0001f, C2 = 0.0009f;

    const int t  = threadIdx.x;
    const int x0 = blockIdx.x * WSTRIP;
    const int y0 = blockIdx.y * HSEG;
    const int y1 = y0 + HSEG;
    const size_t poff = (size_t)blockIdx.z * (size_t)(IMG * IMG);
    const float* ga = A + poff;
    const float* gb = B + poff;
    const float* gf = F + poff;

    // double-buffered 11-row chunks; pre-packed channels:
    //   sAB[.][.][c] = (a, b)   sFQ[.][.][c] = (f, f*f)
    __shared__ u64 sAB[2][11][SROW];
    __shared__ u64 sFQ[2][11][SROW];
    __shared__ float wpart[4];

    // packed (w,w) weights; symmetry -> 6 distinct registers
    u64 W2[6];
#pragma unroll
    for (int j = 0; j < 6; ++j) W2[j] = pk(W[j], W[j]);

    // vertical ring: 4 packed channels x 11 pending output rows
    u64 aAB[11], aAB2[11], aABF[11], aFF[11];
#pragma unroll
    for (int s = 0; s < 11; ++s) { aAB[s] = 0; aAB2[s] = 0; aABF[s] = 0; aFF[s] = 0; }

    float ssum = 0.0f;

    const int ract_lo = (y0 - HALO) < 0 ? 0 : (y0 - HALO);
    const int ract_hi = (y1 + HALO - 1) > (IMG - 1) ? (IMG - 1) : (y1 + HALO - 1);

    const int  c0  = x0 - HALO + t;
    const bool c0v = (c0 >= 0) && (c0 < IMG);
    const int  c1  = c0 + 128;
    const bool c1v = (t < 10) && (c1 < IMG);

    const int base    = ((y0 - HALO + 11) / 11) * 11 - 11;   // multiple of 11 <= y0-5
    const int nchunks = (y1 + HALO - base + 10) / 11;

    // ---- prologue: stage rows base..base+10 into buffer 0 ----
#pragma unroll
    for (int p = 0; p < 11; ++p) {
        const int r = base + p;
        float va = 0, vb = 0, vf = 0, ua = 0, ub = 0, uf = 0;
        if (r >= ract_lo && r <= ract_hi) {
            if (c0v) { const int i = r * IMG + c0; va = ga[i]; vb = gb[i]; vf = gf[i]; }
            if (c1v) { const int i = r * IMG + c1; ua = ga[i]; ub = gb[i]; uf = gf[i]; }
        }
        sAB[0][p][t] = pk(va, vb);
        sFQ[0][p][t] = pk(vf, vf * vf);
        if (t < 10) {
            sAB[0][p][t + 128] = pk(ua, ub);
            sFQ[0][p][t + 128] = pk(uf, uf * uf);
        }
    }
    __syncthreads();

#pragma unroll 1
    for (int chk = 0; chk < nchunks; ++chk) {
        const int rbase = base + chk * 11;
        const int bb = chk & 1, nb = bb ^ 1;
#pragma unroll
        for (int p = 0; p < 11; ++p) {
            const int row = rbase + p;

            // issue global loads for row+11 (next chunk, same phase slot)
            const int nr = row + 11;
            float va = 0, vb = 0, vf = 0, ua = 0, ub = 0, uf = 0;
            if (nr >= ract_lo && nr <= ract_hi) {
                if (c0v) { const int i = nr * IMG + c0; va = ga[i]; vb = gb[i]; vf = gf[i]; }
                if (c1v) { const int i = nr * IMG + c1; ua = ga[i]; ub = gb[i]; uf = gf[i]; }
            }

            if (row >= ract_lo && row <= ract_hi) {
                const u64* rab = sAB[bb][p];
                const u64* rfq = sFQ[bb][p];
                u64 hAB = 0, hAB2 = 0, hABF = 0, hFF = 0;
#pragma unroll
                for (int j = 0; j < 11; ++j) {
                    const u64 w2  = W2[j < 6 ? j : 10 - j];
                    const u64 vab = rab[t + j];
                    const u64 pf  = rfq[t + j];
                    hAB  = fma2(vab, w2, hAB);         // (Sa, Sb)
                    const u64 t1 = mul2(vab, w2);      // (w a, w b)
                    hAB2 = fma2(t1, vab, hAB2);        // (Sa2, Sb2)
                    hFF  = fma2(pf, w2, hFF);          // (Sf, Sf2)
                    float fl, fh; upk(pf, fl, fh);
                    const u64 vff = pk(fl, fl);        // (f, f)
                    hABF = fma2(t1, vff, hABF);        // (Saf, Sbf)
                }
                // vertical scatter into 11 pending outputs (static slots)
#pragma unroll
                for (int j = 0; j < 11; ++j) {
                    const int s  = (p + 6 + j) % 11;
                    const u64 w2 = W2[j < 6 ? j : 10 - j];
                    aAB [s] = fma2(hAB , w2, aAB [s]);
                    aAB2[s] = fma2(hAB2, w2, aAB2[s]);
                    aABF[s] = fma2(hABF, w2, aABF[s]);
                    aFF [s] = fma2(hFF , w2, aFF [s]);
                }
            }

            // output row o = row - 5 is complete in slot (p+6)%11 — scalar epilogue
            {
                const int o  = row - HALO;
                const int sd = (p + 6) % 11;
                if (o >= y0 && o < y1) {
                    float muA, muB, EA2, EB2, EAF, EBF, muF, EF2;
                    upk(aAB [sd], muA, muB);
                    upk(aAB2[sd], EA2, EB2);
                    upk(aABF[sd], EAF, EBF);
                    upk(aFF [sd], muF, EF2);
                    const float muF2 = muF * muF;
                    const float mc   = muF2 + C1;            // mu2^2 + C1 (shared)
                    const float s2   = (EF2 - muF2) + C2;    // sigma2 + C2 (shared)
                    {   // pair (A, F)
                        const float m12 = muA * muF;
                        const float mus = muA * muA;
                        const float num = fmaf(2.0f, m12, C1) * fmaf(2.0f, EAF - m12, C2);
                        const float den = (mus + mc) * ((EA2 - mus) + s2);
                        ssum += __fdividef(num, den);
                    }
                    {   // pair (B, F)
                        const float m12 = muB * muF;
                        const float mus = muB * muB;
                        const float num = fmaf(2.0f, m12, C1) * fmaf(2.0f, EBF - m12, C2);
                        const float den = (mus + mc) * ((EB2 - mus) + s2);
                        ssum += __fdividef(num, den);
                    }
                }
                aAB[sd] = 0; aAB2[sd] = 0; aABF[sd] = 0; aFF[sd] = 0;
            }

            // stage prefetched row into next buffer, same phase slot
            sAB[nb][p][t] = pk(va, vb);
            sFQ[nb][p][t] = pk(vf, vf * vf);
            if (t < 10) {
                sAB[nb][p][t + 128] = pk(ua, ub);
                sFQ[nb][p][t + 128] = pk(uf, uf * uf);
            }
        }
        __syncthreads();
    }

    // block reduction -> single atomic per block
    const unsigned lane = t & 31u;
    const unsigned wid  = (unsigned)t >> 5;
#pragma unroll
    for (int off = 16; off; off >>= 1)
        ssum += __shfl_down_sync(0xffffffffu, ssum, off);
    if (lane == 0) wpart[wid] = ssum;
    __syncthreads();
    if (t == 0)
        atomicAdd(out, (wpart[0] + wpart[1] + wpart[2] + wpart[3]) * scale);
}

__global__ void zero_kernel(float* out) { *out = 0.0f; }

extern "C" void kernel_launch(void* const* d_in, const int* in_sizes, int n_in,
                              void* d_out, int out_size)
{
    const float* A = (const float*)d_in[0];
    const float* B = (const float*)d_in[1];
    const float* F = (const float*)d_in[2];
    float* out = (float*)d_out;

    const int nplanes = in_sizes[0] / (IMG * IMG);   // 48
    const float scale = 0.5f / (float)in_sizes[0];

    zero_kernel<<<1, 1>>>(out);
    dim3 grid(IMG / WSTRIP, IMG / HSEG, nplanes);
    ssim_fused_kernel<<<grid, 128>>>(A, B, F, out, scale);
}